// round 8
// baseline (speedup 1.0000x reference)
#include <cuda_runtime.h>
#include <cuda_fp16.h>

// SinkhornDistance: B=64, N=M=1024, eps=0.1, 50 iterations.
// Scaling domain: K = exp(-C/eps); a = (mu+1e-8)/(K b); b = (nu+1e-8)/(K^T a)
// pi = exp(-C/eps) * a_i * b_j (fp32) ; cost_b = sum pi*C.
// b0 = 1 (valid: pi/cost invariant to b0 scaling; outputs only pi,cost).
//
// R8: 32-row tiles (64KB dynamic smem), 512-thread blocks, two row-halves
// combine column partials in smem before ONE float4 atomic per 4 columns
// -> L2 atomic ops per launch halved (512K -> 256K). 3 blocks/SM, 48 warps.

#define BATCH 64
#define NN 1024
#define INV_EPS 10.0f
#define LOGEPS 1e-8f
#define MAX_ITER 50

#define GSZ 32               // batches per group (2 groups)
#define RPB 32               // rows per block
#define BPB (NN / RPB)       // 32 blocks per batch
#define THREADS 512

// dynamic smem layout (bytes):
//   [0 .. 65536)            uint2 ktile[RPB][256]   (reused as float4 redbuf[256] after phase 2)
//   [65536 .. 66688)        float wsum[RPB][9]
//   [66688 .. 66816)        float mush[RPB]
//   [66816 .. 66944)        float ash[RPB]
#define SMEM_BYTES 66944

// Scratch (static device globals; no runtime allocation)
__device__ __half g_K16[(size_t)BATCH * NN * NN];  // 128 MB
__device__ float g_a[BATCH * NN];
__device__ float g_T[3][BATCH * NN];               // rotation buffers

// ---------------------------------------------------------------------------
// K16 = fp16(exp(-C/eps)) for one group's slab. Thread handles 4 elements.
__global__ void __launch_bounds__(256) k_precompute16(const float* __restrict__ C,
                                                      int group_start) {
    size_t base = (size_t)group_start * NN * NN;
    size_t i = base + ((size_t)blockIdx.x * 256 + threadIdx.x) * 4;
    float4 c = *(const float4*)(C + i);
    __half2 h0 = __floats2half2_rn(__expf(-c.x * INV_EPS), __expf(-c.y * INV_EPS));
    __half2 h1 = __floats2half2_rn(__expf(-c.z * INV_EPS), __expf(-c.w * INV_EPS));
    uint2 pk;
    pk.x = *(const unsigned int*)&h0;
    pk.y = *(const unsigned int*)&h1;
    *(uint2*)(g_K16 + i) = pk;
}

// Zero cost[64] and T[0] for all batches. grid = 64 blocks x 256 threads.
__global__ void k_init(float* __restrict__ cost) {
    int idx = blockIdx.x * 256 + threadIdx.x;  // 16384 float4 = 64K floats
    ((float4*)g_T[0])[idx] = make_float4(0.f, 0.f, 0.f, 0.f);
    if (blockIdx.x == 0 && threadIdx.x < BATCH) cost[threadIdx.x] = 0.0f;
}

// ---------------------------------------------------------------------------
// Fused iteration on fp16 K. Block owns 32 rows of one batch.
// 512 threads: col4 = tid%256 (4 columns), half = tid/256 (16 rows each).
// K tile staged in dynamic smem; K read from L2 exactly once.
// Buffers: read T[(it+2)%3], write T[it%3], zero-ahead T[(it+1)%3].
__global__ void __launch_bounds__(THREADS, 3) fused_iter(
    const float* __restrict__ mu, const float* __restrict__ nu,
    int group_start, int iter)
{
    extern __shared__ char smem[];
    uint2* ktile = (uint2*)smem;                       // [RPB][256]
    float (*wsum)[9] = (float(*)[9])(smem + 65536);    // [RPB][9]
    float* mush = (float*)(smem + 66688);              // [RPB]
    float* ash  = (float*)(smem + 66816);              // [RPB]

    int batch = group_start + blockIdx.x / BPB;
    int r0 = (blockIdx.x % BPB) * RPB;
    int tid = threadIdx.x;
    int lane = tid & 31, warp = tid >> 5;
    int col4 = tid & 255;        // column group (4 cols)
    int half = tid >> 8;         // 0: rows 0-15, 1: rows 16-31
    int rbase = r0 + half * 16;

    // Prefetch mu for this block's 32 rows (retires under phase 1).
    if (tid < RPB) mush[tid] = mu[(size_t)batch * NN + r0 + tid] + LOGEPS;

    // b at this thread's 4 columns (half2 for the phase-1 dot).
    __half2 bh01, bh23;
    if (iter == 0) {
        bh01 = __floats2half2_rn(1.f, 1.f);
        bh23 = bh01;
    } else {
        float4 t = ((const float4*)&g_T[(iter + 2) % 3][(size_t)batch * NN])[col4];
        float4 n = ((const float4*)(nu + (size_t)batch * NN))[col4];
        bh01 = __floats2half2_rn(__fdividef(n.x + LOGEPS, t.x),
                                 __fdividef(n.y + LOGEPS, t.y));
        bh23 = __floats2half2_rn(__fdividef(n.z + LOGEPS, t.z),
                                 __fdividef(n.w + LOGEPS, t.w));
    }

    // Zero-ahead: buffer (iter+1)%3 untouched by other blocks this launch.
    if ((blockIdx.x % BPB) == 0 && tid < 256) {
        ((float4*)&g_T[(iter + 1) % 3][(size_t)batch * NN])[tid] =
            make_float4(0.f, 0.f, 0.f, 0.f);
    }

    const uint2* __restrict__ Kb =
        (const uint2*)(g_K16 + (size_t)batch * NN * NN);

    // Phase 1: 4-row chunks — LDG, half2 dot from registers, stash to smem.
    float part[16];
#pragma unroll
    for (int c = 0; c < 4; c++) {
        uint2 kv[4];
#pragma unroll
        for (int r = 0; r < 4; r++)
            kv[r] = Kb[(size_t)(rbase + c * 4 + r) * (NN / 4) + col4];
#pragma unroll
        for (int r = 0; r < 4; r++) {
            __half2 k01 = *(__half2*)&kv[r].x;
            __half2 k23 = *(__half2*)&kv[r].y;
            __half2 p = __hfma2(k23, bh23, __hmul2(k01, bh01));
            float2 pf = __half22float2(p);
            part[c * 4 + r] = pf.x + pf.y;
            ktile[(half * 16 + c * 4 + r) * 256 + col4] = kv[r];
        }
    }

    // Folded multi-row warp reduce: 31 shfl for 16 rows.
#pragma unroll
    for (int r = 0; r < 16; r++)
        part[r] += __shfl_xor_sync(0xffffffffu, part[r], 16);
    float u8[8];
#pragma unroll
    for (int j = 0; j < 8; j++) {
        u8[j] = (lane & 16) ? part[j + 8] : part[j];
        u8[j] += __shfl_xor_sync(0xffffffffu, u8[j], 8);
    }
    float u4[4];
#pragma unroll
    for (int j = 0; j < 4; j++) {
        u4[j] = (lane & 8) ? u8[j + 4] : u8[j];
        u4[j] += __shfl_xor_sync(0xffffffffu, u4[j], 4);
    }
    float u2[2];
#pragma unroll
    for (int j = 0; j < 2; j++) {
        u2[j] = (lane & 4) ? u4[j + 2] : u4[j];
        u2[j] += __shfl_xor_sync(0xffffffffu, u2[j], 2);
    }
    float q = (lane & 2) ? u2[1] : u2[0];
    q += __shfl_xor_sync(0xffffffffu, q, 1);
    int R = (lane >> 1) & 15;
    if (!(lane & 1)) wsum[half * 16 + R][warp & 7] = q;
    __syncthreads();

    // Tiny critical section: smem-only + fast divide (32 rows).
    if (tid < RPB) {
        float s = 0.f;
#pragma unroll
        for (int w = 0; w < 8; w++) s += wsum[tid][w];
        float a = __fdividef(mush[tid], s);
        ash[tid] = a;
        if (iter == MAX_ITER - 1) g_a[(size_t)batch * NN + r0 + tid] = a;
    }
    __syncthreads();

    // Phase 2: column partials over this half's 16 rows (fp32 accumulate).
    float4 acc = make_float4(0.f, 0.f, 0.f, 0.f);
#pragma unroll
    for (int r = 0; r < 16; r++) {
        float a = ash[half * 16 + r];
        uint2 kv = ktile[(half * 16 + r) * 256 + col4];
        float2 f01 = __half22float2(*(__half2*)&kv.x);
        float2 f23 = __half22float2(*(__half2*)&kv.y);
        acc.x = fmaf(f01.x, a, acc.x);
        acc.y = fmaf(f01.y, a, acc.y);
        acc.z = fmaf(f23.x, a, acc.z);
        acc.w = fmaf(f23.y, a, acc.w);
    }

    // Combine the two halves in smem (reuse ktile region), ONE atomic per col4.
    __syncthreads();   // everyone done reading ktile
    float4* redbuf = (float4*)smem;   // 256 * 16B = 4KB
    if (half == 1) redbuf[col4] = acc;
    __syncthreads();
    if (half == 0) {
        float4 o = redbuf[col4];
        acc.x += o.x; acc.y += o.y; acc.z += o.z; acc.w += o.w;
        float4* T4 = (float4*)(&g_T[iter % 3][(size_t)batch * NN] + col4 * 4);
        atomicAdd(T4, acc);
    }
}

// ---------------------------------------------------------------------------
// Epilogue (per group): read C (fp32), K = exp(-C/eps) on the fly,
// pi = K*a_i*b_j (fp32), cost_b += sum pi*C. Final T buffer: (MAX_ITER-1)%3.
__global__ void __launch_bounds__(256) epilogue(
    const float* __restrict__ C, const float* __restrict__ nu,
    float* __restrict__ out_cost, float* __restrict__ out_pi, int group_start)
{
    __shared__ float bsh[NN];
    const int blocksPerBatch = NN / 8;
    int batch = group_start + blockIdx.x / blocksPerBatch;
    int rowBase = (blockIdx.x % blocksPerBatch) * 8;
    int tid = threadIdx.x;

    const float* __restrict__ T = &g_T[(MAX_ITER - 1) % 3][(size_t)batch * NN];
    for (int j = tid; j < NN; j += 256)
        bsh[j] = (nu[(size_t)batch * NN + j] + LOGEPS) / T[j];
    __syncthreads();

    int warp = tid >> 5, lane = tid & 31;
    int row = rowBase + warp;
    float a = g_a[(size_t)batch * NN + row];
    const float4* __restrict__ Crow =
        (const float4*)(C + ((size_t)batch * NN + row) * NN);
    float4* __restrict__ Prow =
        (float4*)(out_pi + ((size_t)batch * NN + row) * NN);
    const float4* __restrict__ bsh4 = (const float4*)bsh;

    float cacc = 0.0f;
#pragma unroll
    for (int k = 0; k < 8; k++) {
        int idx = k * 32 + lane;
        float4 cv = Crow[idx];
        float4 bv = bsh4[idx];
        float4 p;
        p.x = __expf(-cv.x * INV_EPS) * a * bv.x;
        p.y = __expf(-cv.y * INV_EPS) * a * bv.y;
        p.z = __expf(-cv.z * INV_EPS) * a * bv.z;
        p.w = __expf(-cv.w * INV_EPS) * a * bv.w;
        cacc += p.x * cv.x + p.y * cv.y + p.z * cv.z + p.w * cv.w;
        Prow[idx] = p;
    }
#pragma unroll
    for (int o = 16; o; o >>= 1) cacc += __shfl_xor_sync(0xffffffffu, cacc, o);
    if (lane == 0) atomicAdd(&out_cost[batch], cacc);
}

// ---------------------------------------------------------------------------
extern "C" void kernel_launch(void* const* d_in, const int* in_sizes, int n_in,
                              void* d_out, int out_size) {
    const float* mu = (const float*)d_in[0];
    const float* nu = (const float*)d_in[1];
    const float* C  = (const float*)d_in[2];
    float* cost = (float*)d_out;                 // outputs: (cost[64], pi[64M])
    float* pi   = (float*)d_out + BATCH;

    cudaFuncSetAttribute(fused_iter,
                         cudaFuncAttributeMaxDynamicSharedMemorySize, SMEM_BYTES);

    k_init<<<64, 256>>>(cost);

    const int precompBlocks = GSZ * NN * NN / (256 * 4);  // 32768
    for (int g = 0; g < BATCH / GSZ; g++) {
        int start = g * GSZ;
        k_precompute16<<<precompBlocks, 256>>>(C, start);
        for (int it = 0; it < MAX_ITER; it++) {
            fused_iter<<<GSZ * BPB, THREADS, SMEM_BYTES>>>(mu, nu, start, it);
        }
        epilogue<<<GSZ * (NN / 8), 256>>>(C, nu, cost, pi, start);
    }
}

// round 9
// speedup vs baseline: 1.0332x; 1.0332x over previous
#include <cuda_runtime.h>
#include <cuda_fp16.h>

// SinkhornDistance: B=64, N=M=1024, eps=0.1, 50 iterations.
// Scaling domain: K = exp(-C/eps); a = (mu+1e-8)/(K b); b = (nu+1e-8)/(K^T a)
// pi = exp(-C/eps) * a_i * b_j (fp32) ; cost_b = sum pi*C.
// b0 = 1 (valid: pi/cost invariant to b0 scaling; outputs only pi,cost).
//
// R9 = R7 (best) + half2 phase-2 accumulation with a pre-scaled by 4096
// (keeps fp16 partials in normal range; scale cancels in b = nu*4096/T).
// Saves ~80 instr/thread (64 FFMA + 32 cvt -> 32 HFMA2 + 16 cvt).

#define BATCH 64
#define NN 1024
#define INV_EPS 10.0f
#define LOGEPS 1e-8f
#define MAX_ITER 50
#define ASCALE 4096.0f       // 2^12, exact

#define GSZ 32               // batches per group (2 groups)
#define RPB 16               // rows per block
#define BPB (NN / RPB)       // 64 blocks per batch

// Scratch (static device globals; no runtime allocation)
__device__ __half g_K16[(size_t)BATCH * NN * NN];  // 128 MB
__device__ float g_a[BATCH * NN];
__device__ float g_T[3][BATCH * NN];               // rotation buffers (scaled)

// ---------------------------------------------------------------------------
// K16 = fp16(exp(-C/eps)) for one group's slab. Thread handles 4 elements.
__global__ void __launch_bounds__(256) k_precompute16(const float* __restrict__ C,
                                                      int group_start) {
    size_t base = (size_t)group_start * NN * NN;
    size_t i = base + ((size_t)blockIdx.x * 256 + threadIdx.x) * 4;
    float4 c = *(const float4*)(C + i);
    __half2 h0 = __floats2half2_rn(__expf(-c.x * INV_EPS), __expf(-c.y * INV_EPS));
    __half2 h1 = __floats2half2_rn(__expf(-c.z * INV_EPS), __expf(-c.w * INV_EPS));
    uint2 pk;
    pk.x = *(const unsigned int*)&h0;
    pk.y = *(const unsigned int*)&h1;
    *(uint2*)(g_K16 + i) = pk;
}

// Zero cost[64] and T[0] for all batches. grid = 64 blocks x 256 threads.
__global__ void k_init(float* __restrict__ cost) {
    int idx = blockIdx.x * 256 + threadIdx.x;  // 16384 float4 = 64K floats
    ((float4*)g_T[0])[idx] = make_float4(0.f, 0.f, 0.f, 0.f);
    if (blockIdx.x == 0 && threadIdx.x < BATCH) cost[threadIdx.x] = 0.0f;
}

// ---------------------------------------------------------------------------
// Fused iteration on fp16 K. Block owns 16 rows of one batch; thread owns 4
// columns. K tile staged in smem (32KB); K read from L2 exactly once.
// T buffers hold SCALED column sums (x ASCALE).
// Buffers: read T[(it+2)%3], write T[it%3], zero-ahead T[(it+1)%3].
__global__ void __launch_bounds__(256) fused_iter(
    const float* __restrict__ mu, const float* __restrict__ nu,
    int group_start, int iter)
{
    int batch = group_start + blockIdx.x / BPB;
    int r0 = (blockIdx.x % BPB) * RPB;
    int tid = threadIdx.x;
    int lane = tid & 31, warp = tid >> 5;

    __shared__ uint2 ktile[RPB][256];     // 32 KB fp16 tile stash
    __shared__ float mush[RPB];
    __shared__ float ash[RPB];            // a * ASCALE
    __shared__ float wsum[RPB][9];        // padded

    // Prefetch mu for this block's rows (retires under phase 1).
    if (tid < RPB) mush[tid] = mu[(size_t)batch * NN + r0 + tid] + LOGEPS;

    // b (true scale) at this thread's 4 columns, half2 for the phase-1 dot.
    // T is scaled by ASCALE, so multiply nu by ASCALE: cancels exactly.
    __half2 bh01, bh23;
    if (iter == 0) {
        bh01 = __floats2half2_rn(1.f, 1.f);
        bh23 = bh01;
    } else {
        float4 t = ((const float4*)&g_T[(iter + 2) % 3][(size_t)batch * NN])[tid];
        float4 n = ((const float4*)(nu + (size_t)batch * NN))[tid];
        bh01 = __floats2half2_rn(__fdividef((n.x + LOGEPS) * ASCALE, t.x),
                                 __fdividef((n.y + LOGEPS) * ASCALE, t.y));
        bh23 = __floats2half2_rn(__fdividef((n.z + LOGEPS) * ASCALE, t.z),
                                 __fdividef((n.w + LOGEPS) * ASCALE, t.w));
    }

    // Zero-ahead: buffer (iter+1)%3 is untouched by all other blocks this
    // launch (last read was the previous launch) -> race-free.
    if ((blockIdx.x % BPB) == 0) {
        ((float4*)&g_T[(iter + 1) % 3][(size_t)batch * NN])[tid] =
            make_float4(0.f, 0.f, 0.f, 0.f);
    }

    const uint2* __restrict__ Kb =
        (const uint2*)(g_K16 + (size_t)batch * NN * NN);

    // Phase 1: 4-row chunks — LDG, half2 dot from registers, stash to smem.
    float part[RPB];
#pragma unroll
    for (int c = 0; c < RPB / 4; c++) {
        uint2 kv[4];
#pragma unroll
        for (int r = 0; r < 4; r++)
            kv[r] = Kb[(size_t)(r0 + c * 4 + r) * (NN / 4) + tid];
#pragma unroll
        for (int r = 0; r < 4; r++) {
            __half2 k01 = *(__half2*)&kv[r].x;
            __half2 k23 = *(__half2*)&kv[r].y;
            __half2 p = __hfma2(k23, bh23, __hmul2(k01, bh01));
            float2 pf = __half22float2(p);
            part[c * 4 + r] = pf.x + pf.y;
            ktile[c * 4 + r][tid] = kv[r];
        }
    }

    // Folded multi-row warp reduce: 31 shfl for 16 rows.
#pragma unroll
    for (int r = 0; r < RPB; r++)
        part[r] += __shfl_xor_sync(0xffffffffu, part[r], 16);
    float u8[8];
#pragma unroll
    for (int j = 0; j < 8; j++) {
        u8[j] = (lane & 16) ? part[j + 8] : part[j];
        u8[j] += __shfl_xor_sync(0xffffffffu, u8[j], 8);
    }
    float u4[4];
#pragma unroll
    for (int j = 0; j < 4; j++) {
        u4[j] = (lane & 8) ? u8[j + 4] : u8[j];
        u4[j] += __shfl_xor_sync(0xffffffffu, u4[j], 4);
    }
    float u2[2];
#pragma unroll
    for (int j = 0; j < 2; j++) {
        u2[j] = (lane & 4) ? u4[j + 2] : u4[j];
        u2[j] += __shfl_xor_sync(0xffffffffu, u2[j], 2);
    }
    float q = (lane & 2) ? u2[1] : u2[0];
    q += __shfl_xor_sync(0xffffffffu, q, 1);
    int R = (lane >> 1) & 15;
    if (!(lane & 1)) wsum[R][warp] = q;
    __syncthreads();

    // Tiny critical section: smem-only + fast divide.
    if (tid < RPB) {
        float s = 0.f;
#pragma unroll
        for (int w = 0; w < 8; w++) s += wsum[tid][w];
        float a = __fdividef(mush[tid], s);          // true a
        ash[tid] = a * ASCALE;                        // scaled for fp16 phase 2
        if (iter == MAX_ITER - 1) g_a[(size_t)batch * NN + r0 + tid] = a;
    }
    __syncthreads();

    // Phase 2: column partials in half2 (values kept in normal fp16 range by
    // the ASCALE pre-scaling of a).
    __half2 acc01 = __floats2half2_rn(0.f, 0.f);
    __half2 acc23 = acc01;
#pragma unroll
    for (int r = 0; r < RPB; r++) {
        __half2 ah = __float2half2_rn(ash[r]);
        uint2 kv = ktile[r][tid];
        acc01 = __hfma2(*(__half2*)&kv.x, ah, acc01);
        acc23 = __hfma2(*(__half2*)&kv.y, ah, acc23);
    }
    float2 a01 = __half22float2(acc01);
    float2 a23 = __half22float2(acc23);
    float4 accf = make_float4(a01.x, a01.y, a23.x, a23.y);

    // Single vector atomic per thread (sm_90+).
    float4* T4 = (float4*)(&g_T[iter % 3][(size_t)batch * NN] + tid * 4);
    atomicAdd(T4, accf);
}

// ---------------------------------------------------------------------------
// Epilogue (per group): read C (fp32), K = exp(-C/eps) on the fly,
// pi = K*a_i*b_j (fp32), cost_b += sum pi*C. Final T buffer: (MAX_ITER-1)%3.
// T is scaled by ASCALE -> multiply nu by ASCALE (cancels).
__global__ void __launch_bounds__(256) epilogue(
    const float* __restrict__ C, const float* __restrict__ nu,
    float* __restrict__ out_cost, float* __restrict__ out_pi, int group_start)
{
    __shared__ float bsh[NN];
    const int blocksPerBatch = NN / 8;
    int batch = group_start + blockIdx.x / blocksPerBatch;
    int rowBase = (blockIdx.x % blocksPerBatch) * 8;
    int tid = threadIdx.x;

    const float* __restrict__ T = &g_T[(MAX_ITER - 1) % 3][(size_t)batch * NN];
    for (int j = tid; j < NN; j += 256)
        bsh[j] = (nu[(size_t)batch * NN + j] + LOGEPS) * ASCALE / T[j];
    __syncthreads();

    int warp = tid >> 5, lane = tid & 31;
    int row = rowBase + warp;
    float a = g_a[(size_t)batch * NN + row];
    const float4* __restrict__ Crow =
        (const float4*)(C + ((size_t)batch * NN + row) * NN);
    float4* __restrict__ Prow =
        (float4*)(out_pi + ((size_t)batch * NN + row) * NN);
    const float4* __restrict__ bsh4 = (const float4*)bsh;

    float cacc = 0.0f;
#pragma unroll
    for (int k = 0; k < 8; k++) {
        int idx = k * 32 + lane;
        float4 cv = Crow[idx];
        float4 bv = bsh4[idx];
        float4 p;
        p.x = __expf(-cv.x * INV_EPS) * a * bv.x;
        p.y = __expf(-cv.y * INV_EPS) * a * bv.y;
        p.z = __expf(-cv.z * INV_EPS) * a * bv.z;
        p.w = __expf(-cv.w * INV_EPS) * a * bv.w;
        cacc += p.x * cv.x + p.y * cv.y + p.z * cv.z + p.w * cv.w;
        Prow[idx] = p;
    }
#pragma unroll
    for (int o = 16; o; o >>= 1) cacc += __shfl_xor_sync(0xffffffffu, cacc, o);
    if (lane == 0) atomicAdd(&out_cost[batch], cacc);
}

// ---------------------------------------------------------------------------
extern "C" void kernel_launch(void* const* d_in, const int* in_sizes, int n_in,
                              void* d_out, int out_size) {
    const float* mu = (const float*)d_in[0];
    const float* nu = (const float*)d_in[1];
    const float* C  = (const float*)d_in[2];
    float* cost = (float*)d_out;                 // outputs: (cost[64], pi[64M])
    float* pi   = (float*)d_out + BATCH;

    k_init<<<64, 256>>>(cost);

    const int precompBlocks = GSZ * NN * NN / (256 * 4);  // 32768
    for (int g = 0; g < BATCH / GSZ; g++) {
        int start = g * GSZ;
        k_precompute16<<<precompBlocks, 256>>>(C, start);
        for (int it = 0; it < MAX_ITER; it++) {
            fused_iter<<<GSZ * BPB, 256>>>(mu, nu, start, it);
        }
        epilogue<<<GSZ * (NN / 8), 256>>>(C, nu, cost, pi, start);
    }
}

// round 10
// speedup vs baseline: 1.1247x; 1.0886x over previous
#include <cuda_runtime.h>
#include <cuda_fp16.h>

// SinkhornDistance: B=64, N=M=1024, eps=0.1, 50 iterations.
// Scaling domain: K = exp(-C/eps); a = (mu+1e-8)/(K b); b = (nu+1e-8)/(K^T a)
// pi = exp(-C/eps) * a_i * b_j (fp32) ; cost_b = sum pi*C.  b0 = 1 (scale-invariant).
//
// R10: ONE persistent kernel, K tiles resident in SHARED MEMORY for all 50
// iterations (zero K traffic per epoch). Teams of 64 blocks own one batch per
// round; per-batch dataflow sync: release-written epoch flag + acquire spin
// (no nanosleep). K built from C on the fly at round start (no g_K16, no
// precompute kernel). Epilogue folded in (exact fp32 pi from C re-read).
// Grid sized from occupancy query -> co-residency guaranteed.

#define BATCH 64
#define NN 1024
#define INV_EPS 10.0f
#define LOGEPS 1e-8f
#define MAX_ITER 50
#define ASCALE 4096.0f       // 2^12, exact; cancels in b = nu*ASCALE/T_scaled

#define RPB 16               // rows per block
#define BPB 64               // blocks per team (= NN/RPB)

// Scratch (static device globals; no runtime allocation)
__device__ float g_T[3][BATCH * NN];     // rotation buffers (scaled col sums)
__device__ unsigned g_cnt[BATCH];        // arrival counters (monotonic)
__device__ unsigned g_flag[BATCH];       // completed-epoch flag (monotonic)

__device__ __forceinline__ unsigned ld_acq(const unsigned* p) {
    unsigned v;
    asm volatile("ld.acquire.gpu.b32 %0, [%1];" : "=r"(v) : "l"(p) : "memory");
    return v;
}
__device__ __forceinline__ void st_rel(unsigned* p, unsigned v) {
    asm volatile("st.release.gpu.b32 [%0], %1;" :: "l"(p), "r"(v) : "memory");
}

// ---------------------------------------------------------------------------
// Zero T[0] (all batches), cost, counters, flags. grid = 64 x 256.
__global__ void k_init(float* __restrict__ cost) {
    int idx = blockIdx.x * 256 + threadIdx.x;  // 16384 float4 = 64K floats
    ((float4*)g_T[0])[idx] = make_float4(0.f, 0.f, 0.f, 0.f);
    if (blockIdx.x == 0 && threadIdx.x < BATCH) {
        cost[threadIdx.x] = 0.0f;
        g_cnt[threadIdx.x] = 0u;
        g_flag[threadIdx.x] = 0u;
    }
}

// ---------------------------------------------------------------------------
__global__ void __launch_bounds__(256, 6) sinkhorn_resident(
    const float* __restrict__ mu, const float* __restrict__ nu,
    const float* __restrict__ C, float* __restrict__ cost,
    float* __restrict__ pi, int teams)
{
    const int team = blockIdx.x >> 6;    // /BPB
    const int blk  = blockIdx.x & 63;
    const int r0   = blk * RPB;
    const int tid  = threadIdx.x;
    const int lane = tid & 31, warp = tid >> 5;

    __shared__ uint2 ktile[RPB][256];    // 32 KB fp16 K tile (round-resident)
    __shared__ float mush[RPB];
    __shared__ float ash[RPB];           // a * ASCALE (for half2 phase 2)
    __shared__ float atrue[RPB];         // true a (for epilogue)
    __shared__ float wsum[RPB][9];       // padded

    for (int batch = team; batch < BATCH; batch += teams) {
        // ---- round setup: mu, nu, and the smem-resident K tile from C ----
        if (tid < RPB) mush[tid] = mu[(size_t)batch * NN + r0 + tid] + LOGEPS;
        float4 nv = ((const float4*)(nu + (size_t)batch * NN))[tid];
        nv.x = (nv.x + LOGEPS) * ASCALE;
        nv.y = (nv.y + LOGEPS) * ASCALE;
        nv.z = (nv.z + LOGEPS) * ASCALE;
        nv.w = (nv.w + LOGEPS) * ASCALE;

#pragma unroll
        for (int r = 0; r < RPB; r++) {
            float4 c = ((const float4*)(C + ((size_t)batch * NN + r0 + r) * NN))[tid];
            __half2 h0 = __floats2half2_rn(__expf(-c.x * INV_EPS),
                                           __expf(-c.y * INV_EPS));
            __half2 h1 = __floats2half2_rn(__expf(-c.z * INV_EPS),
                                           __expf(-c.w * INV_EPS));
            uint2 pk;
            pk.x = *(const unsigned*)&h0;
            pk.y = *(const unsigned*)&h1;
            ktile[r][tid] = pk;   // each thread only ever reads its own slot
        }

        unsigned* cntp  = &g_cnt[batch];
        unsigned* flagp = &g_flag[batch];

        // ---- 50 iterations, dataflow-synced across the 64-block team ----
        for (int it = 0; it < MAX_ITER; it++) {
            if (it > 0) {
                if (tid == 0) {
                    while (ld_acq(flagp) < (unsigned)it) { }
                }
                __syncthreads();
            }

            __half2 bh01, bh23;
            if (it == 0) {
                bh01 = __floats2half2_rn(1.f, 1.f);
                bh23 = bh01;
            } else {
                float4 t = ((const float4*)&g_T[(it + 2) % 3][(size_t)batch * NN])[tid];
                bh01 = __floats2half2_rn(__fdividef(nv.x, t.x),
                                         __fdividef(nv.y, t.y));
                bh23 = __floats2half2_rn(__fdividef(nv.z, t.z),
                                         __fdividef(nv.w, t.w));
            }

            // Zero-ahead: all blocks passed epoch it-1, so T[(it+1)%3] has no
            // remaining readers (last read was at epoch it-1). Race-free.
            if (blk == 0)
                ((float4*)&g_T[(it + 1) % 3][(size_t)batch * NN])[tid] =
                    make_float4(0.f, 0.f, 0.f, 0.f);

            // Phase 1: row dots from the smem-resident tile (half2).
            float part[RPB];
#pragma unroll
            for (int r = 0; r < RPB; r++) {
                uint2 kv = ktile[r][tid];
                __half2 p = __hfma2(*(__half2*)&kv.y, bh23,
                                    __hmul2(*(__half2*)&kv.x, bh01));
                float2 pf = __half22float2(p);
                part[r] = pf.x + pf.y;
            }
            // Folded multi-row warp reduce: 31 shfl for 16 rows.
#pragma unroll
            for (int r = 0; r < RPB; r++)
                part[r] += __shfl_xor_sync(0xffffffffu, part[r], 16);
            float u8[8];
#pragma unroll
            for (int j = 0; j < 8; j++) {
                u8[j] = (lane & 16) ? part[j + 8] : part[j];
                u8[j] += __shfl_xor_sync(0xffffffffu, u8[j], 8);
            }
            float u4[4];
#pragma unroll
            for (int j = 0; j < 4; j++) {
                u4[j] = (lane & 8) ? u8[j + 4] : u8[j];
                u4[j] += __shfl_xor_sync(0xffffffffu, u4[j], 4);
            }
            float u2[2];
#pragma unroll
            for (int j = 0; j < 2; j++) {
                u2[j] = (lane & 4) ? u4[j + 2] : u4[j];
                u2[j] += __shfl_xor_sync(0xffffffffu, u2[j], 2);
            }
            float q = (lane & 2) ? u2[1] : u2[0];
            q += __shfl_xor_sync(0xffffffffu, q, 1);
            int R = (lane >> 1) & 15;
            if (!(lane & 1)) wsum[R][warp] = q;
            __syncthreads();

            if (tid < RPB) {
                float s = 0.f;
#pragma unroll
                for (int w = 0; w < 8; w++) s += wsum[tid][w];
                float a = __fdividef(mush[tid], s);
                atrue[tid] = a;
                ash[tid] = a * ASCALE;
            }
            __syncthreads();

            // Phase 2: scaled half2 column partials from the smem tile.
            __half2 acc01 = __floats2half2_rn(0.f, 0.f);
            __half2 acc23 = acc01;
#pragma unroll
            for (int r = 0; r < RPB; r++) {
                __half2 ah = __float2half2_rn(ash[r]);
                uint2 kv = ktile[r][tid];
                acc01 = __hfma2(*(__half2*)&kv.x, ah, acc01);
                acc23 = __hfma2(*(__half2*)&kv.y, ah, acc23);
            }
            float2 a01 = __half22float2(acc01);
            float2 a23 = __half22float2(acc23);
            atomicAdd((float4*)(&g_T[it % 3][(size_t)batch * NN] + tid * 4),
                      make_float4(a01.x, a01.y, a23.x, a23.y));

            // Arrive: all 256 threads' atomics done -> fence -> count -> flag.
            __syncthreads();
            if (tid == 0) {
                __threadfence();
                unsigned old = atomicAdd(cntp, 1u);
                if ((old & 63u) == 63u) st_rel(flagp, (unsigned)(it + 1));
            }
        }

        // ---- epilogue for this batch (needs all final T contributions) ----
        if (tid == 0) {
            while (ld_acq(flagp) < (unsigned)MAX_ITER) { }
        }
        __syncthreads();

        float4 t = ((const float4*)&g_T[(MAX_ITER - 1) % 3][(size_t)batch * NN])[tid];
        float4 bv;
        bv.x = nv.x / t.x;
        bv.y = nv.y / t.y;
        bv.z = nv.z / t.z;
        bv.w = nv.w / t.w;

        float cacc = 0.0f;
#pragma unroll
        for (int r = 0; r < RPB; r++) {
            float a = atrue[r];
            float4 cv = ((const float4*)(C + ((size_t)batch * NN + r0 + r) * NN))[tid];
            float4 p;
            p.x = __expf(-cv.x * INV_EPS) * a * bv.x;
            p.y = __expf(-cv.y * INV_EPS) * a * bv.y;
            p.z = __expf(-cv.z * INV_EPS) * a * bv.z;
            p.w = __expf(-cv.w * INV_EPS) * a * bv.w;
            cacc += p.x * cv.x + p.y * cv.y + p.z * cv.z + p.w * cv.w;
            ((float4*)(pi + ((size_t)batch * NN + r0 + r) * NN))[tid] = p;
        }
#pragma unroll
        for (int o = 16; o; o >>= 1)
            cacc += __shfl_xor_sync(0xffffffffu, cacc, o);
        if (lane == 0) wsum[warp][0] = cacc;
        __syncthreads();
        if (tid == 0) {
            float s = 0.f;
#pragma unroll
            for (int w = 0; w < 8; w++) s += wsum[w][0];
            atomicAdd(&cost[batch], s);
        }
        __syncthreads();   // protect wsum/ktile reuse in the next round
    }
}

// ---------------------------------------------------------------------------
extern "C" void kernel_launch(void* const* d_in, const int* in_sizes, int n_in,
                              void* d_out, int out_size) {
    const float* mu = (const float*)d_in[0];
    const float* nu = (const float*)d_in[1];
    const float* C  = (const float*)d_in[2];
    float* cost = (float*)d_out;                 // outputs: (cost[64], pi[64M])
    float* pi   = (float*)d_out + BATCH;

    // Co-residency-safe grid size (pure queries; deterministic per machine).
    int occ = 0, sms = 0, dev = 0;
    cudaGetDevice(&dev);
    cudaOccupancyMaxActiveBlocksPerMultiprocessor(&occ, sinkhorn_resident, 256, 0);
    cudaDeviceGetAttribute(&sms, cudaDevAttrMultiProcessorCount, dev);
    int teams = (occ * sms) / BPB;
    if (teams > BATCH) teams = BATCH;
    if (teams < 1) teams = 1;

    k_init<<<64, 256>>>(cost);
    sinkhorn_resident<<<teams * BPB, 256>>>(mu, nu, C, cost, pi, teams);
}